// round 10
// baseline (speedup 1.0000x reference)
#include <cuda_runtime.h>
#include <cuda_bf16.h>
#include <cstdint>

// Problem constants
#define BATCH   4
#define SEQ     6144
#define DIM     384
#define FCHUNK  3
#define NB      12      // BATCH*FCHUNK
#define LEN     2048    // SEQ/FCHUNK
#define DIN     192     // DIM/2
#define DSTATE  16
#define DTRANK  24
#define MTOT    (NB*LEN)    // 24576

// ---------------------------------------------------------------------------
// Scratch (static __device__ arrays; no allocation allowed)
// ---------------------------------------------------------------------------
__device__ float g_xp[MTOT * DIM];           // (12,2048,384) in_proj output
__device__ float g_xc[NB * DIN * LEN];       // (b,d,l) conv+silu output
__device__ float g_dt[NB * DTRANK * LEN];    // (b,r,l)
__device__ float g_Bm[NB * LEN * DSTATE];    // (b,l,n)
__device__ float g_Cm[NB * LEN * DSTATE];    // (b,l,n)
__device__ float g_delta[NB * DIN * LEN];    // (b,d,l)
__device__ float g_yf[NB * DIN * LEN];       // fwd scan out; later fused ysum
__device__ float g_yb[NB * DIN * LEN];       // bwd scan out (b,d,l)

// ---------------------------------------------------------------------------
// helpers
// ---------------------------------------------------------------------------
__device__ __forceinline__ uint32_t smem_u32(const void* p) {
    uint32_t a;
    asm("{ .reg .u64 t; cvta.to.shared.u64 t, %1; cvt.u32.u64 %0, t; }"
        : "=r"(a) : "l"(p));
    return a;
}
__device__ __forceinline__ uint32_t f2tf32(float x) {
    uint32_t r;
    asm("cvt.rna.tf32.f32 %0, %1;" : "=r"(r) : "f"(x));
    return r;
}
__device__ __forceinline__ void cp16(uint32_t dst, const void* src) {
    asm volatile("cp.async.ca.shared.global [%0], [%1], 16;"
                 :: "r"(dst), "l"(src) : "memory");
}
#define CP_COMMIT() asm volatile("cp.async.commit_group;" ::: "memory")
#define CP_WAIT1()  asm volatile("cp.async.wait_group 1;" ::: "memory")
#define CP_WAIT0()  asm volatile("cp.async.wait_group 0;" ::: "memory")

__device__ __forceinline__ void mma_tf32(float* c, const uint32_t* a,
                                         const uint32_t* b) {
    asm volatile(
        "mma.sync.aligned.m16n8k8.row.col.f32.tf32.tf32.f32 "
        "{%0,%1,%2,%3}, {%4,%5,%6,%7}, {%8,%9}, {%0,%1,%2,%3};"
        : "+f"(c[0]), "+f"(c[1]), "+f"(c[2]), "+f"(c[3])
        : "r"(a[0]), "r"(a[1]), "r"(a[2]), "r"(a[3]), "r"(b[0]), "r"(b[1]));
}

// ---------------------------------------------------------------------------
// tf32 HMMA GEMM: C[M,384] = A[M,384] @ W[384,384]^T + bias
// MODE 0: A plain row-major [m][k] (in_proj). MODE 1: A from (d,l) layout
// (k<192 -> g_yf fused ysum, else g_xc). 128x128 tile, BK=32,
// 2-stage cp.async pipeline (73.7KB smem -> 2 CTAs/SM).
// ---------------------------------------------------------------------------
#define AS_STRIDE0 36
#define AS_STRIDE1 136
#define BS_STRIDE  36
#define AS_F0 (128 * AS_STRIDE0)
#define AS_F1 (32 * AS_STRIDE1)
#define BS_F  (128 * BS_STRIDE)
#define GEMM_SMEM0 ((2 * (AS_F0 + BS_F)) * 4)   // 73728 B
#define GEMM_SMEM1 ((2 * (AS_F1 + BS_F)) * 4)   // 71680 B

template <int MODE>
__global__ __launch_bounds__(256, 2)
void gemm_tf32_kernel(const float* __restrict__ A,
                      const float* __restrict__ W,
                      const float* __restrict__ bias,
                      float* __restrict__ C)
{
    extern __shared__ float smf[];
    constexpr int AS_F = (MODE == 0) ? AS_F0 : AS_F1;
    float* AsBuf = smf;
    float* BsBuf = smf + 2 * AS_F;

    const int tid  = threadIdx.x;
    const int wid  = tid >> 5;
    const int lane = tid & 31;
    const int g = lane >> 2;
    const int t = lane & 3;
    const int wm = wid >> 1;
    const int wn = wid & 1;

    const int m0 = blockIdx.y * 128;
    const int n0 = blockIdx.x * 128;
    const int bb = m0 >> 11;
    const int lbase = m0 & 2047;

    const uint32_t sAu = smem_u32(AsBuf);
    const uint32_t sBu = smem_u32(BsBuf);

    float acc[2][8][4];
#pragma unroll
    for (int mt = 0; mt < 2; mt++)
#pragma unroll
        for (int nt = 0; nt < 8; nt++)
#pragma unroll
            for (int q = 0; q < 4; q++) acc[mt][nt][q] = 0.f;

    auto load_tile = [&](int kt, int buf) {
        const int k0 = kt * 32;
#pragma unroll
        for (int it = 0; it < 4; it++) {
            int idx = it * 256 + tid;
            int r = idx >> 3, c4 = idx & 7;
            uint32_t dst = sBu + (buf * BS_F + r * BS_STRIDE + c4 * 4) * 4;
            cp16(dst, &W[(n0 + r) * DIM + k0 + c4 * 4]);
        }
        if (MODE == 0) {
#pragma unroll
            for (int it = 0; it < 4; it++) {
                int idx = it * 256 + tid;
                int r = idx >> 3, c4 = idx & 7;
                uint32_t dst = sAu + (buf * AS_F + r * AS_STRIDE0 + c4 * 4) * 4;
                cp16(dst, &A[(m0 + r) * DIM + k0 + c4 * 4]);
            }
        } else {
            const float* srcb = (k0 < DIN)
                ? g_yf + ((size_t)(bb * DIN + k0) * LEN)
                : g_xc + ((size_t)(bb * DIN + (k0 - DIN)) * LEN);
#pragma unroll
            for (int it = 0; it < 4; it++) {
                int idx = it * 256 + tid;
                int kk = idx >> 5, m4 = idx & 31;
                uint32_t dst = sAu + (buf * AS_F + kk * AS_STRIDE1 + m4 * 4) * 4;
                cp16(dst, srcb + (size_t)kk * LEN + lbase + m4 * 4);
            }
        }
        CP_COMMIT();
    };

    load_tile(0, 0);

    for (int kt = 0; kt < 12; kt++) {
        if (kt + 1 < 12) {
            load_tile(kt + 1, (kt + 1) & 1);
            CP_WAIT1();
        } else {
            CP_WAIT0();
        }
        __syncthreads();

        const int buf = kt & 1;
        const float* As = AsBuf + buf * AS_F;
        const float* Bs = BsBuf + buf * BS_F;

#pragma unroll
        for (int s = 0; s < 4; s++) {
            uint32_t bf[8][2];
#pragma unroll
            for (int nt = 0; nt < 8; nt++) {
                int n = wn * 64 + nt * 8 + g;
                bf[nt][0] = f2tf32(Bs[n * BS_STRIDE + s * 8 + t]);
                bf[nt][1] = f2tf32(Bs[n * BS_STRIDE + s * 8 + t + 4]);
            }
#pragma unroll
            for (int mt = 0; mt < 2; mt++) {
                int row = wm * 32 + mt * 16 + g;
                uint32_t af[4];
                if (MODE == 0) {
                    af[0] = f2tf32(As[row * AS_STRIDE0 + s * 8 + t]);
                    af[1] = f2tf32(As[(row + 8) * AS_STRIDE0 + s * 8 + t]);
                    af[2] = f2tf32(As[row * AS_STRIDE0 + s * 8 + t + 4]);
                    af[3] = f2tf32(As[(row + 8) * AS_STRIDE0 + s * 8 + t + 4]);
                } else {
                    af[0] = f2tf32(As[(s * 8 + t) * AS_STRIDE1 + row]);
                    af[1] = f2tf32(As[(s * 8 + t) * AS_STRIDE1 + row + 8]);
                    af[2] = f2tf32(As[(s * 8 + t + 4) * AS_STRIDE1 + row]);
                    af[3] = f2tf32(As[(s * 8 + t + 4) * AS_STRIDE1 + row + 8]);
                }
#pragma unroll
                for (int nt = 0; nt < 8; nt++)
                    mma_tf32(acc[mt][nt], af, bf[nt]);
            }
        }
        __syncthreads();
    }

#pragma unroll
    for (int mt = 0; mt < 2; mt++) {
        int row = m0 + wm * 32 + mt * 16 + g;
#pragma unroll
        for (int nt = 0; nt < 8; nt++) {
            int col = n0 + wn * 64 + nt * 8 + t * 2;
            float b0 = bias[col], b1 = bias[col + 1];
            float2 v0 = make_float2(acc[mt][nt][0] + b0, acc[mt][nt][1] + b1);
            float2 v1 = make_float2(acc[mt][nt][2] + b0, acc[mt][nt][3] + b1);
            *(float2*)&C[(size_t)row * DIM + col] = v0;
            *(float2*)&C[(size_t)(row + 8) * DIM + col] = v1;
        }
    }
}

// ---------------------------------------------------------------------------
// Grouped conv (k=3, SAME, groups=192, 2 in-ch per group) + SiLU
// ---------------------------------------------------------------------------
__global__ __launch_bounds__(1024)
void conv_silu_kernel(const float* __restrict__ conv_w,
                      const float* __restrict__ conv_b)
{
    __shared__ float s[34][65];
    const int b  = blockIdx.z;
    const int d0 = blockIdx.y * 32;
    const int l0 = blockIdx.x * 32;
    const int tid = threadIdx.y * 32 + threadIdx.x;

    for (int e = tid; e < 34 * 64; e += 1024) {
        int li = e >> 6;
        int ci = e & 63;
        int l = l0 - 1 + li;
        float v = 0.f;
        if (l >= 0 && l < LEN)
            v = g_xp[(b * LEN + l) * DIM + 2 * d0 + ci];
        s[li][ci] = v;
    }
    __syncthreads();

    const int tx = threadIdx.x, ty = threadIdx.y;
    const int d = d0 + ty;
    float acc = conv_b[d];
    const float* w = conv_w + d * 6;
#pragma unroll
    for (int i = 0; i < 2; i++)
#pragma unroll
        for (int j = 0; j < 3; j++)
            acc = fmaf(s[tx + j][2 * ty + i], w[i * 3 + j], acc);
    float y = acc / (1.f + __expf(-acc));
    g_xc[(b * DIN + d) * LEN + l0 + tx] = y;
}

// ---------------------------------------------------------------------------
// x_proj: x_dbl[b,r,l] = sum_d W[r,d]*xc[b,d,l]; r-chunk 28 over blockIdx.z
// ---------------------------------------------------------------------------
__global__ __launch_bounds__(128)
void xproj_kernel(const float* __restrict__ x_proj_w)
{
    __shared__ float sW[28 * DIN];
    const int b = blockIdx.y;
    const int l = blockIdx.x * 128 + threadIdx.x;
    const int r0 = blockIdx.z * 28;

    for (int i = threadIdx.x; i < 28 * DIN; i += 128)
        sW[i] = x_proj_w[r0 * DIN + i];
    __syncthreads();

    float acc[28];
#pragma unroll
    for (int j = 0; j < 28; j++) acc[j] = 0.f;

    for (int d = 0; d < DIN; d++) {
        float v = g_xc[(b * DIN + d) * LEN + l];
#pragma unroll
        for (int j = 0; j < 28; j++)
            acc[j] = fmaf(sW[j * DIN + d], v, acc[j]);
    }
#pragma unroll
    for (int j = 0; j < 28; j++) {
        int r = r0 + j;
        if (r < DTRANK)
            g_dt[(b * DTRANK + r) * LEN + l] = acc[j];
        else if (r < DTRANK + DSTATE)
            g_Bm[(b * LEN + l) * DSTATE + (r - DTRANK)] = acc[j];
        else
            g_Cm[(b * LEN + l) * DSTATE + (r - DTRANK - DSTATE)] = acc[j];
    }
}

// ---------------------------------------------------------------------------
// delta[b,d,l] = softplus(dt_proj_w[d,:].dt[b,:,l] + dt_proj_b[d]); d-chunk 24
// ---------------------------------------------------------------------------
__global__ __launch_bounds__(128)
void delta_kernel(const float* __restrict__ dt_proj_w,
                  const float* __restrict__ dt_proj_b)
{
    __shared__ float sW[24 * DTRANK];
    const int b = blockIdx.y;
    const int l = blockIdx.x * 128 + threadIdx.x;
    const int d0 = blockIdx.z * 24;

    for (int i = threadIdx.x; i < 24 * DTRANK; i += 128)
        sW[i] = dt_proj_w[d0 * DTRANK + i];
    __syncthreads();

    float dt[DTRANK];
#pragma unroll
    for (int r = 0; r < DTRANK; r++)
        dt[r] = g_dt[(b * DTRANK + r) * LEN + l];

#pragma unroll 4
    for (int j = 0; j < 24; j++) {
        int d = d0 + j;
        float a = dt_proj_b[d];
#pragma unroll
        for (int r = 0; r < DTRANK; r++)
            a = fmaf(sW[j * DTRANK + r], dt[r], a);
        float sp = (a > 20.f) ? a : log1pf(__expf(a));
        g_delta[(b * DIN + d) * LEN + l] = sp;
    }
}

// ---------------------------------------------------------------------------
// Bidirectional selective scan v2.1 — R6 skeleton (separate fully-unrolled
// fwd/bwd loops) with float4 del/u loads and batched MUFU.
// Block: 256 thr / 8 warps, owns (b, 8 consecutive d's).
// ---------------------------------------------------------------------------
#define SCHUNK   64
#define SC_BUF   6272
#define SC_DU    4096
#define SC_SMEM  (2 * SC_BUF * 4)   // 50176 B

__global__ __launch_bounds__(256)
void scan_kernel(const float* __restrict__ A_log,
                 const float* __restrict__ Ab_log)
{
    extern __shared__ float ss[];
    const int b  = blockIdx.x / (DIN / 8);
    const int d0 = (blockIdx.x % (DIN / 8)) * 8;
    const int tid = threadIdx.x;
    const int wid = tid >> 5, lane = tid & 31;
    const bool bwd = wid >= 4;
    const int w = bwd ? wid - 4 : wid;
    const int half = lane >> 4, n = lane & 15;
    const int dloc = 2 * w + half;
    const int dg = d0 + dloc;

    const float Aval = -__expf(bwd ? Ab_log[dg * DSTATE + n]
                                   : A_log[dg * DSTATE + n]);
    float* yptr = (bwd ? g_yb : g_yf) + (size_t)(b * DIN + dg) * LEN;

    const uint32_t sbase = smem_u32(ss);

    auto load_chunk = [&](int c, int buf) {
        const uint32_t dstb = sbase + (uint32_t)buf * SC_BUF * 4;
        const int lf = c * SCHUNK;
        const int lb = LEN - (c + 1) * SCHUNK;
#pragma unroll
        for (int it = 0; it < 4; it++) {
            int task = it * 256 + tid;
            int arr = task >> 8, r = task & 255;
            int lo = r >> 2, n4 = (r & 3) * 4;
            int ls = (arr < 2) ? lf + lo : lb + lo;
            const float* src = ((arr & 1) ? g_Cm : g_Bm)
                + ((size_t)(b * LEN + ls) * DSTATE + n4);
            cp16(dstb + (uint32_t)(arr * 1024 + lo * 16 + n4) * 4, src);
        }
#pragma unroll
        for (int it = 0; it < 2; it++) {
            int q = it * 256 + tid;
            int arr = q >> 7, s = q & 127;
            int dl = s >> 4, l4 = (s & 15) * 4;
            int ls = (arr < 2) ? lf + l4 : lb + l4;
            const float* src = ((arr & 1) ? g_xc : g_delta)
                + ((size_t)(b * DIN + d0 + dl) * LEN + ls);
            cp16(dstb + (uint32_t)(SC_DU + arr * 544 + dl * 68 + l4) * 4, src);
        }
    };

    float h = 0.f;
    load_chunk(0, 0);
    CP_COMMIT();

    for (int c = 0; c < LEN / SCHUNK; c++) {
        const int buf = c & 1;
        if (c + 1 < LEN / SCHUNK) load_chunk(c + 1, buf ^ 1);
        CP_COMMIT();
        CP_WAIT1();
        __syncthreads();

        const float* sm   = ss + buf * SC_BUF;
        const float* sB   = sm + (bwd ? 2048 : 0);
        const float* sC   = sB + 1024;
        const float* sdel = sm + SC_DU + (bwd ? 1088 : 0) + dloc * 68;
        const float* su   = sdel + 544;

        if (!bwd) {
            const int tg = c * SCHUNK;
#pragma unroll
            for (int j4 = 0; j4 < 16; j4++) {
                const int t0 = j4 * 4;
                float4 d4 = *(const float4*)&sdel[t0];
                float4 u4 = *(const float4*)&su[t0];
                float dA0 = __expf(d4.x * Aval);
                float dA1 = __expf(d4.y * Aval);
                float dA2 = __expf(d4.z * Aval);
                float dA3 = __expf(d4.w * Aval);
                float p[4];
                h = fmaf(dA0, h, d4.x * u4.x * sB[(t0 + 0) * 16 + n]);
                p[0] = h * sC[(t0 + 0) * 16 + n];
                h = fmaf(dA1, h, d4.y * u4.y * sB[(t0 + 1) * 16 + n]);
                p[1] = h * sC[(t0 + 1) * 16 + n];
                h = fmaf(dA2, h, d4.z * u4.z * sB[(t0 + 2) * 16 + n]);
                p[2] = h * sC[(t0 + 2) * 16 + n];
                h = fmaf(dA3, h, d4.w * u4.w * sB[(t0 + 3) * 16 + n]);
                p[3] = h * sC[(t0 + 3) * 16 + n];
#pragma unroll
                for (int k = 0; k < 4; k++) {
                    p[k] += __shfl_xor_sync(0xffffffffu, p[k], 1);
                    p[k] += __shfl_xor_sync(0xffffffffu, p[k], 2);
                    p[k] += __shfl_xor_sync(0xffffffffu, p[k], 4);
                    p[k] += __shfl_xor_sync(0xffffffffu, p[k], 8);
                }
                if (n == 0)
                    *(float4*)&yptr[tg + t0] =
                        make_float4(p[0], p[1], p[2], p[3]);
            }
        } else {
            const int tg = LEN - (c + 1) * SCHUNK;
#pragma unroll
            for (int j4 = 15; j4 >= 0; j4--) {
                const int t0 = j4 * 4;
                float4 d4 = *(const float4*)&sdel[t0];
                float4 u4 = *(const float4*)&su[t0];
                float dA0 = __expf(d4.x * Aval);
                float dA1 = __expf(d4.y * Aval);
                float dA2 = __expf(d4.z * Aval);
                float dA3 = __expf(d4.w * Aval);
                float p[4];
                h = fmaf(dA3, h, d4.w * u4.w * sB[(t0 + 3) * 16 + n]);
                p[3] = h * sC[(t0 + 3) * 16 + n];
                h = fmaf(dA2, h, d4.z * u4.z * sB[(t0 + 2) * 16 + n]);
                p[2] = h * sC[(t0 + 2) * 16 + n];
                h = fmaf(dA1, h, d4.y * u4.y * sB[(t0 + 1) * 16 + n]);
                p[1] = h * sC[(t0 + 1) * 16 + n];
                h = fmaf(dA0, h, d4.x * u4.x * sB[(t0 + 0) * 16 + n]);
                p[0] = h * sC[(t0 + 0) * 16 + n];
#pragma unroll
                for (int k = 0; k < 4; k++) {
                    p[k] += __shfl_xor_sync(0xffffffffu, p[k], 1);
                    p[k] += __shfl_xor_sync(0xffffffffu, p[k], 2);
                    p[k] += __shfl_xor_sync(0xffffffffu, p[k], 4);
                    p[k] += __shfl_xor_sync(0xffffffffu, p[k], 8);
                }
                if (n == 0)
                    *(float4*)&yptr[tg + t0] =
                        make_float4(p[0], p[1], p[2], p[3]);
            }
        }
        __syncthreads();
    }
}

// ---------------------------------------------------------------------------
// fuse: g_yf = yf + yb + 2*D[d]*xc   (elementwise, (b,d,l) layout)
// ---------------------------------------------------------------------------
__global__ __launch_bounds__(256)
void fuse_kernel(const float* __restrict__ Dv)
{
    const int total4 = NB * DIN * LEN / 4;
    for (int i4 = blockIdx.x * blockDim.x + threadIdx.x; i4 < total4;
         i4 += gridDim.x * blockDim.x) {
        int d = (i4 >> 9) % DIN;
        float dd = 2.f * Dv[d];
        float4 yf4 = ((const float4*)g_yf)[i4];
        float4 yb4 = ((const float4*)g_yb)[i4];
        float4 xc4 = ((const float4*)g_xc)[i4];
        float4 o;
        o.x = yf4.x + yb4.x + dd * xc4.x;
        o.y = yf4.y + yb4.y + dd * xc4.y;
        o.z = yf4.z + yb4.z + dd * xc4.z;
        o.w = yf4.w + yb4.w + dd * xc4.w;
        ((float4*)g_yf)[i4] = o;
    }
}

// ---------------------------------------------------------------------------
// Launch
// ---------------------------------------------------------------------------
extern "C" void kernel_launch(void* const* d_in, const int* in_sizes, int n_in,
                              void* d_out, int out_size)
{
    (void)in_sizes; (void)n_in; (void)out_size;
    const float* x          = (const float*)d_in[0];
    const float* in_proj_w  = (const float*)d_in[1];
    const float* in_proj_b  = (const float*)d_in[2];
    const float* conv_w     = (const float*)d_in[3];
    const float* conv_b     = (const float*)d_in[4];
    const float* A_log      = (const float*)d_in[5];
    const float* Ab_log     = (const float*)d_in[6];
    const float* Dv         = (const float*)d_in[7];
    const float* x_proj_w   = (const float*)d_in[8];
    const float* dt_proj_w  = (const float*)d_in[9];
    const float* dt_proj_b  = (const float*)d_in[10];
    const float* out_proj_w = (const float*)d_in[11];
    const float* out_proj_b = (const float*)d_in[12];
    float* out = (float*)d_out;

    float* xp_ptr;
    cudaGetSymbolAddress((void**)&xp_ptr, g_xp);

    cudaFuncSetAttribute(gemm_tf32_kernel<0>,
                         cudaFuncAttributeMaxDynamicSharedMemorySize, GEMM_SMEM0);
    cudaFuncSetAttribute(gemm_tf32_kernel<1>,
                         cudaFuncAttributeMaxDynamicSharedMemorySize, GEMM_SMEM1);
    cudaFuncSetAttribute(scan_kernel,
                         cudaFuncAttributeMaxDynamicSharedMemorySize, SC_SMEM);

    // 1. in_proj GEMM (tf32 HMMA, 2-stage, 2 CTA/SM) -> g_xp
    gemm_tf32_kernel<0><<<dim3(DIM / 128, MTOT / 128), 256, GEMM_SMEM0>>>(
        x, in_proj_w, in_proj_b, xp_ptr);

    // 2. conv + silu -> g_xc
    conv_silu_kernel<<<dim3(LEN / 32, DIN / 32, NB), dim3(32, 32)>>>(
        conv_w, conv_b);

    // 3. x_proj split -> g_dt, g_Bm, g_Cm  (r-chunk 2)
    xproj_kernel<<<dim3(LEN / 128, NB, 2), 128>>>(x_proj_w);

    // 4. delta = softplus(dt_proj) -> g_delta   (profiled slot)
    delta_kernel<<<dim3(LEN / 128, NB, 8), 128>>>(dt_proj_w, dt_proj_b);

    // 5. bidirectional scan v2.1 -> g_yf, g_yb
    scan_kernel<<<NB * (DIN / 8), 256, SC_SMEM>>>(A_log, Ab_log);

    // 6. fuse ysum = yf + yb + 2*D*xc -> g_yf
    fuse_kernel<<<1024, 256>>>(Dv);

    // 7. out_proj GEMM (tf32 HMMA, 2-stage, (d,l)-layout A) -> d_out
    gemm_tf32_kernel<1><<<dim3(DIM / 128, MTOT / 128), 256, GEMM_SMEM1>>>(
        nullptr, out_proj_w, out_proj_b, out);
}

// round 11
// speedup vs baseline: 1.0328x; 1.0328x over previous
#include <cuda_runtime.h>
#include <cuda_bf16.h>
#include <cstdint>

// Problem constants
#define BATCH   4
#define SEQ     6144
#define DIM     384
#define FCHUNK  3
#define NB      12      // BATCH*FCHUNK
#define LEN     2048    // SEQ/FCHUNK
#define DIN     192     // DIM/2
#define DSTATE  16
#define DTRANK  24
#define MTOT    (NB*LEN)    // 24576

// ---------------------------------------------------------------------------
// Scratch (static __device__ arrays; no allocation allowed)
// ---------------------------------------------------------------------------
__device__ float g_xp[MTOT * DIM];           // (12,2048,384) in_proj output
__device__ float g_xc[NB * DIN * LEN];       // (b,d,l) conv+silu output
__device__ float g_dt[NB * DTRANK * LEN];    // (b,r,l)
__device__ float g_BC[NB * LEN * 2 * DSTATE];// (b,l,n,2) interleaved B/C
__device__ float g_delta[NB * DIN * LEN];    // (b,d,l)
__device__ float g_yf[NB * DIN * LEN];       // fwd scan out; later fused ysum
__device__ float g_yb[NB * DIN * LEN];       // bwd scan out (b,d,l)

// ---------------------------------------------------------------------------
// helpers
// ---------------------------------------------------------------------------
__device__ __forceinline__ uint32_t smem_u32(const void* p) {
    uint32_t a;
    asm("{ .reg .u64 t; cvta.to.shared.u64 t, %1; cvt.u32.u64 %0, t; }"
        : "=r"(a) : "l"(p));
    return a;
}
__device__ __forceinline__ uint32_t f2tf32(float x) {
    uint32_t r;
    asm("cvt.rna.tf32.f32 %0, %1;" : "=r"(r) : "f"(x));
    return r;
}
__device__ __forceinline__ void cp16(uint32_t dst, const void* src) {
    asm volatile("cp.async.ca.shared.global [%0], [%1], 16;"
                 :: "r"(dst), "l"(src) : "memory");
}
#define CP_COMMIT() asm volatile("cp.async.commit_group;" ::: "memory")
#define CP_WAIT1()  asm volatile("cp.async.wait_group 1;" ::: "memory")
#define CP_WAIT0()  asm volatile("cp.async.wait_group 0;" ::: "memory")

__device__ __forceinline__ void mma_tf32(float* c, const uint32_t* a,
                                         const uint32_t* b) {
    asm volatile(
        "mma.sync.aligned.m16n8k8.row.col.f32.tf32.tf32.f32 "
        "{%0,%1,%2,%3}, {%4,%5,%6,%7}, {%8,%9}, {%0,%1,%2,%3};"
        : "+f"(c[0]), "+f"(c[1]), "+f"(c[2]), "+f"(c[3])
        : "r"(a[0]), "r"(a[1]), "r"(a[2]), "r"(a[3]), "r"(b[0]), "r"(b[1]));
}

// ---------------------------------------------------------------------------
// tf32 HMMA GEMM: C[M,384] = A[M,384] @ W[384,384]^T + bias
// MODE 0: A plain row-major [m][k] (in_proj). MODE 1: A from (d,l) layout
// (k<192 -> g_yf fused ysum, else g_xc). 128x128 tile, BK=32,
// 2-stage cp.async pipeline (73.7KB smem -> 2 CTAs/SM).
// ---------------------------------------------------------------------------
#define AS_STRIDE0 36
#define AS_STRIDE1 136
#define BS_STRIDE  36
#define AS_F0 (128 * AS_STRIDE0)
#define AS_F1 (32 * AS_STRIDE1)
#define BS_F  (128 * BS_STRIDE)
#define GEMM_SMEM0 ((2 * (AS_F0 + BS_F)) * 4)   // 73728 B
#define GEMM_SMEM1 ((2 * (AS_F1 + BS_F)) * 4)   // 71680 B

template <int MODE>
__global__ __launch_bounds__(256, 2)
void gemm_tf32_kernel(const float* __restrict__ A,
                      const float* __restrict__ W,
                      const float* __restrict__ bias,
                      float* __restrict__ C)
{
    extern __shared__ float smf[];
    constexpr int AS_F = (MODE == 0) ? AS_F0 : AS_F1;
    float* AsBuf = smf;
    float* BsBuf = smf + 2 * AS_F;

    const int tid  = threadIdx.x;
    const int wid  = tid >> 5;
    const int lane = tid & 31;
    const int g = lane >> 2;
    const int t = lane & 3;
    const int wm = wid >> 1;
    const int wn = wid & 1;

    const int m0 = blockIdx.y * 128;
    const int n0 = blockIdx.x * 128;
    const int bb = m0 >> 11;
    const int lbase = m0 & 2047;

    const uint32_t sAu = smem_u32(AsBuf);
    const uint32_t sBu = smem_u32(BsBuf);

    float acc[2][8][4];
#pragma unroll
    for (int mt = 0; mt < 2; mt++)
#pragma unroll
        for (int nt = 0; nt < 8; nt++)
#pragma unroll
            for (int q = 0; q < 4; q++) acc[mt][nt][q] = 0.f;

    auto load_tile = [&](int kt, int buf) {
        const int k0 = kt * 32;
#pragma unroll
        for (int it = 0; it < 4; it++) {
            int idx = it * 256 + tid;
            int r = idx >> 3, c4 = idx & 7;
            uint32_t dst = sBu + (buf * BS_F + r * BS_STRIDE + c4 * 4) * 4;
            cp16(dst, &W[(n0 + r) * DIM + k0 + c4 * 4]);
        }
        if (MODE == 0) {
#pragma unroll
            for (int it = 0; it < 4; it++) {
                int idx = it * 256 + tid;
                int r = idx >> 3, c4 = idx & 7;
                uint32_t dst = sAu + (buf * AS_F + r * AS_STRIDE0 + c4 * 4) * 4;
                cp16(dst, &A[(m0 + r) * DIM + k0 + c4 * 4]);
            }
        } else {
            const float* srcb = (k0 < DIN)
                ? g_yf + ((size_t)(bb * DIN + k0) * LEN)
                : g_xc + ((size_t)(bb * DIN + (k0 - DIN)) * LEN);
#pragma unroll
            for (int it = 0; it < 4; it++) {
                int idx = it * 256 + tid;
                int kk = idx >> 5, m4 = idx & 31;
                uint32_t dst = sAu + (buf * AS_F + kk * AS_STRIDE1 + m4 * 4) * 4;
                cp16(dst, srcb + (size_t)kk * LEN + lbase + m4 * 4);
            }
        }
        CP_COMMIT();
    };

    load_tile(0, 0);

    for (int kt = 0; kt < 12; kt++) {
        if (kt + 1 < 12) {
            load_tile(kt + 1, (kt + 1) & 1);
            CP_WAIT1();
        } else {
            CP_WAIT0();
        }
        __syncthreads();

        const int buf = kt & 1;
        const float* As = AsBuf + buf * AS_F;
        const float* Bs = BsBuf + buf * BS_F;

#pragma unroll
        for (int s = 0; s < 4; s++) {
            uint32_t bf[8][2];
#pragma unroll
            for (int nt = 0; nt < 8; nt++) {
                int n = wn * 64 + nt * 8 + g;
                bf[nt][0] = f2tf32(Bs[n * BS_STRIDE + s * 8 + t]);
                bf[nt][1] = f2tf32(Bs[n * BS_STRIDE + s * 8 + t + 4]);
            }
#pragma unroll
            for (int mt = 0; mt < 2; mt++) {
                int row = wm * 32 + mt * 16 + g;
                uint32_t af[4];
                if (MODE == 0) {
                    af[0] = f2tf32(As[row * AS_STRIDE0 + s * 8 + t]);
                    af[1] = f2tf32(As[(row + 8) * AS_STRIDE0 + s * 8 + t]);
                    af[2] = f2tf32(As[row * AS_STRIDE0 + s * 8 + t + 4]);
                    af[3] = f2tf32(As[(row + 8) * AS_STRIDE0 + s * 8 + t + 4]);
                } else {
                    af[0] = f2tf32(As[(s * 8 + t) * AS_STRIDE1 + row]);
                    af[1] = f2tf32(As[(s * 8 + t) * AS_STRIDE1 + row + 8]);
                    af[2] = f2tf32(As[(s * 8 + t + 4) * AS_STRIDE1 + row]);
                    af[3] = f2tf32(As[(s * 8 + t + 4) * AS_STRIDE1 + row + 8]);
                }
#pragma unroll
                for (int nt = 0; nt < 8; nt++)
                    mma_tf32(acc[mt][nt], af, bf[nt]);
            }
        }
        __syncthreads();
    }

#pragma unroll
    for (int mt = 0; mt < 2; mt++) {
        int row = m0 + wm * 32 + mt * 16 + g;
#pragma unroll
        for (int nt = 0; nt < 8; nt++) {
            int col = n0 + wn * 64 + nt * 8 + t * 2;
            float b0 = bias[col], b1 = bias[col + 1];
            float2 v0 = make_float2(acc[mt][nt][0] + b0, acc[mt][nt][1] + b1);
            float2 v1 = make_float2(acc[mt][nt][2] + b0, acc[mt][nt][3] + b1);
            *(float2*)&C[(size_t)row * DIM + col] = v0;
            *(float2*)&C[(size_t)(row + 8) * DIM + col] = v1;
        }
    }
}

// ---------------------------------------------------------------------------
// Grouped conv (k=3, SAME, groups=192, 2 in-ch per group) + SiLU
// ---------------------------------------------------------------------------
__global__ __launch_bounds__(1024)
void conv_silu_kernel(const float* __restrict__ conv_w,
                      const float* __restrict__ conv_b)
{
    __shared__ float s[34][65];
    const int b  = blockIdx.z;
    const int d0 = blockIdx.y * 32;
    const int l0 = blockIdx.x * 32;
    const int tid = threadIdx.y * 32 + threadIdx.x;

    for (int e = tid; e < 34 * 64; e += 1024) {
        int li = e >> 6;
        int ci = e & 63;
        int l = l0 - 1 + li;
        float v = 0.f;
        if (l >= 0 && l < LEN)
            v = g_xp[(b * LEN + l) * DIM + 2 * d0 + ci];
        s[li][ci] = v;
    }
    __syncthreads();

    const int tx = threadIdx.x, ty = threadIdx.y;
    const int d = d0 + ty;
    float acc = conv_b[d];
    const float* w = conv_w + d * 6;
#pragma unroll
    for (int i = 0; i < 2; i++)
#pragma unroll
        for (int j = 0; j < 3; j++)
            acc = fmaf(s[tx + j][2 * ty + i], w[i * 3 + j], acc);
    float y = acc / (1.f + __expf(-acc));
    g_xc[(b * DIN + d) * LEN + l0 + tx] = y;
}

// ---------------------------------------------------------------------------
// x_proj: x_dbl[b,r,l] = sum_d W[r,d]*xc[b,d,l]; r-chunk 14 over blockIdx.z
// B/C written INTERLEAVED into g_BC[b,l,n,2].
// ---------------------------------------------------------------------------
__global__ __launch_bounds__(128)
void xproj_kernel(const float* __restrict__ x_proj_w)
{
    __shared__ float sW[14 * DIN];
    const int b = blockIdx.y;
    const int l = blockIdx.x * 128 + threadIdx.x;
    const int r0 = blockIdx.z * 14;

    for (int i = threadIdx.x; i < 14 * DIN; i += 128)
        sW[i] = x_proj_w[r0 * DIN + i];
    __syncthreads();

    float acc[14];
#pragma unroll
    for (int j = 0; j < 14; j++) acc[j] = 0.f;

    for (int d = 0; d < DIN; d++) {
        float v = g_xc[(b * DIN + d) * LEN + l];
#pragma unroll
        for (int j = 0; j < 14; j++)
            acc[j] = fmaf(sW[j * DIN + d], v, acc[j]);
    }
#pragma unroll
    for (int j = 0; j < 14; j++) {
        int r = r0 + j;
        if (r < DTRANK)
            g_dt[(b * DTRANK + r) * LEN + l] = acc[j];
        else if (r < DTRANK + DSTATE)
            g_BC[(size_t)(b * LEN + l) * 32 + 2 * (r - DTRANK)] = acc[j];
        else
            g_BC[(size_t)(b * LEN + l) * 32 + 2 * (r - DTRANK - DSTATE) + 1] = acc[j];
    }
}

// ---------------------------------------------------------------------------
// delta[b,d,l] = softplus(dt_proj_w[d,:].dt[b,:,l] + dt_proj_b[d]); d-chunk 24
// ---------------------------------------------------------------------------
__global__ __launch_bounds__(128)
void delta_kernel(const float* __restrict__ dt_proj_w,
                  const float* __restrict__ dt_proj_b)
{
    __shared__ float sW[24 * DTRANK];
    const int b = blockIdx.y;
    const int l = blockIdx.x * 128 + threadIdx.x;
    const int d0 = blockIdx.z * 24;

    for (int i = threadIdx.x; i < 24 * DTRANK; i += 128)
        sW[i] = dt_proj_w[d0 * DTRANK + i];
    __syncthreads();

    float dt[DTRANK];
#pragma unroll
    for (int r = 0; r < DTRANK; r++)
        dt[r] = g_dt[(b * DTRANK + r) * LEN + l];

#pragma unroll 4
    for (int j = 0; j < 24; j++) {
        int d = d0 + j;
        float a = dt_proj_b[d];
#pragma unroll
        for (int r = 0; r < DTRANK; r++)
            a = fmaf(sW[j * DTRANK + r], dt[r], a);
        float sp = (a > 20.f) ? a : log1pf(__expf(a));
        g_delta[(b * DIN + d) * LEN + l] = sp;
    }
}

// ---------------------------------------------------------------------------
// Bidirectional selective scan v2.2 — R9 skeleton, B/C via one LDS.64.
// Block: 256 thr / 8 warps, owns (b, 8 consecutive d's).
//   warps 0-3: forward (d-locals {2w, 2w+1}), warps 4-7: backward (same).
// smem/buffer: BCf[64][32] BCb[64][32] (4096) + del/u f/b [8][68] (2176)
//            = 6272 floats; double buffered = 50176 B.
// ---------------------------------------------------------------------------
#define SCHUNK   64
#define SC_BUF   6272
#define SC_DU    4096
#define SC_SMEM  (2 * SC_BUF * 4)   // 50176 B

__global__ __launch_bounds__(256)
void scan_kernel(const float* __restrict__ A_log,
                 const float* __restrict__ Ab_log)
{
    extern __shared__ float ss[];
    const int b  = blockIdx.x / (DIN / 8);
    const int d0 = (blockIdx.x % (DIN / 8)) * 8;
    const int tid = threadIdx.x;
    const int wid = tid >> 5, lane = tid & 31;
    const bool bwd = wid >= 4;
    const int w = bwd ? wid - 4 : wid;
    const int half = lane >> 4, n = lane & 15;
    const int dloc = 2 * w + half;
    const int dg = d0 + dloc;

    const float Aval = -__expf(bwd ? Ab_log[dg * DSTATE + n]
                                   : A_log[dg * DSTATE + n]);
    float* yptr = (bwd ? g_yb : g_yf) + (size_t)(b * DIN + dg) * LEN;

    const uint32_t sbase = smem_u32(ss);

    auto load_chunk = [&](int c, int buf) {
        const uint32_t dstb = sbase + (uint32_t)buf * SC_BUF * 4;
        const int lf = c * SCHUNK;
        const int lb = LEN - (c + 1) * SCHUNK;
        // BC tiles: arr 0 = fwd range, 1 = bwd range; 512 float4 each
#pragma unroll
        for (int it = 0; it < 4; it++) {
            int task = it * 256 + tid;          // 0..1023
            int arr = task >> 9, r = task & 511;
            int lo = r >> 3, c4 = (r & 7) * 4;
            int ls = arr ? lb + lo : lf + lo;
            cp16(dstb + (uint32_t)(arr * 2048 + lo * 32 + c4) * 4,
                 g_BC + ((size_t)(b * LEN + ls) * 32 + c4));
        }
        // del/u: arr 0=del_f 1=u_f 2=del_b 3=u_b ; 128 float4 each
#pragma unroll
        for (int it = 0; it < 2; it++) {
            int q = it * 256 + tid;
            int arr = q >> 7, s = q & 127;
            int dl = s >> 4, l4 = (s & 15) * 4;
            int ls = (arr < 2) ? lf + l4 : lb + l4;
            const float* src = ((arr & 1) ? g_xc : g_delta)
                + ((size_t)(b * DIN + d0 + dl) * LEN + ls);
            cp16(dstb + (uint32_t)(SC_DU + arr * 544 + dl * 68 + l4) * 4, src);
        }
    };

    float h = 0.f;
    load_chunk(0, 0);
    CP_COMMIT();

    for (int c = 0; c < LEN / SCHUNK; c++) {
        const int buf = c & 1;
        if (c + 1 < LEN / SCHUNK) load_chunk(c + 1, buf ^ 1);
        CP_COMMIT();
        CP_WAIT1();
        __syncthreads();

        const float* sm   = ss + buf * SC_BUF;
        const float* sBC  = sm + (bwd ? 2048 : 0);
        const float* sdel = sm + SC_DU + (bwd ? 1088 : 0) + dloc * 68;
        const float* su   = sdel + 544;
        const int n2 = 2 * n;

        if (!bwd) {
            const int tg = c * SCHUNK;
#pragma unroll
            for (int j4 = 0; j4 < 16; j4++) {
                float p[4];
#pragma unroll
                for (int k = 0; k < 4; k++) {
                    int t = j4 * 4 + k;
                    float del = sdel[t], u = su[t];
                    float2 bc = *(const float2*)&sBC[t * 32 + n2];
                    float dA = __expf(del * Aval);
                    h = fmaf(dA, h, del * u * bc.x);
                    p[k] = h * bc.y;
                }
#pragma unroll
                for (int k = 0; k < 4; k++) {
                    p[k] += __shfl_xor_sync(0xffffffffu, p[k], 1);
                    p[k] += __shfl_xor_sync(0xffffffffu, p[k], 2);
                    p[k] += __shfl_xor_sync(0xffffffffu, p[k], 4);
                    p[k] += __shfl_xor_sync(0xffffffffu, p[k], 8);
                }
                if (n == 0)
                    *(float4*)&yptr[tg + j4 * 4] =
                        make_float4(p[0], p[1], p[2], p[3]);
            }
        } else {
            const int tg = LEN - (c + 1) * SCHUNK;
#pragma unroll
            for (int j4 = 15; j4 >= 0; j4--) {
                float p[4];
#pragma unroll
                for (int k = 0; k < 4; k++) {
                    int t = j4 * 4 + (3 - k);
                    float del = sdel[t], u = su[t];
                    float2 bc = *(const float2*)&sBC[t * 32 + n2];
                    float dA = __expf(del * Aval);
                    h = fmaf(dA, h, del * u * bc.x);
                    p[k] = h * bc.y;
                }
#pragma unroll
                for (int k = 0; k < 4; k++) {
                    p[k] += __shfl_xor_sync(0xffffffffu, p[k], 1);
                    p[k] += __shfl_xor_sync(0xffffffffu, p[k], 2);
                    p[k] += __shfl_xor_sync(0xffffffffu, p[k], 4);
                    p[k] += __shfl_xor_sync(0xffffffffu, p[k], 8);
                }
                if (n == 0)
                    *(float4*)&yptr[tg + j4 * 4] =
                        make_float4(p[3], p[2], p[1], p[0]);
            }
        }
        __syncthreads();
    }
}

// ---------------------------------------------------------------------------
// fuse: g_yf = yf + yb + 2*D[d]*xc   (elementwise, (b,d,l) layout)
// ---------------------------------------------------------------------------
__global__ __launch_bounds__(256)
void fuse_kernel(const float* __restrict__ Dv)
{
    const int total4 = NB * DIN * LEN / 4;
    for (int i4 = blockIdx.x * blockDim.x + threadIdx.x; i4 < total4;
         i4 += gridDim.x * blockDim.x) {
        int d = (i4 >> 9) % DIN;
        float dd = 2.f * Dv[d];
        float4 yf4 = ((const float4*)g_yf)[i4];
        float4 yb4 = ((const float4*)g_yb)[i4];
        float4 xc4 = ((const float4*)g_xc)[i4];
        float4 o;
        o.x = yf4.x + yb4.x + dd * xc4.x;
        o.y = yf4.y + yb4.y + dd * xc4.y;
        o.z = yf4.z + yb4.z + dd * xc4.z;
        o.w = yf4.w + yb4.w + dd * xc4.w;
        ((float4*)g_yf)[i4] = o;
    }
}

// ---------------------------------------------------------------------------
// Launch
// ---------------------------------------------------------------------------
extern "C" void kernel_launch(void* const* d_in, const int* in_sizes, int n_in,
                              void* d_out, int out_size)
{
    (void)in_sizes; (void)n_in; (void)out_size;
    const float* x          = (const float*)d_in[0];
    const float* in_proj_w  = (const float*)d_in[1];
    const float* in_proj_b  = (const float*)d_in[2];
    const float* conv_w     = (const float*)d_in[3];
    const float* conv_b     = (const float*)d_in[4];
    const float* A_log      = (const float*)d_in[5];
    const float* Ab_log     = (const float*)d_in[6];
    const float* Dv         = (const float*)d_in[7];
    const float* x_proj_w   = (const float*)d_in[8];
    const float* dt_proj_w  = (const float*)d_in[9];
    const float* dt_proj_b  = (const float*)d_in[10];
    const float* out_proj_w = (const float*)d_in[11];
    const float* out_proj_b = (const float*)d_in[12];
    float* out = (float*)d_out;

    float* xp_ptr;
    cudaGetSymbolAddress((void**)&xp_ptr, g_xp);

    cudaFuncSetAttribute(gemm_tf32_kernel<0>,
                         cudaFuncAttributeMaxDynamicSharedMemorySize, GEMM_SMEM0);
    cudaFuncSetAttribute(gemm_tf32_kernel<1>,
                         cudaFuncAttributeMaxDynamicSharedMemorySize, GEMM_SMEM1);
    cudaFuncSetAttribute(scan_kernel,
                         cudaFuncAttributeMaxDynamicSharedMemorySize, SC_SMEM);

    // 1. in_proj GEMM (tf32 HMMA, 2-stage, 2 CTA/SM) -> g_xp
    gemm_tf32_kernel<0><<<dim3(DIM / 128, MTOT / 128), 256, GEMM_SMEM0>>>(
        x, in_proj_w, in_proj_b, xp_ptr);

    // 2. conv + silu -> g_xc
    conv_silu_kernel<<<dim3(LEN / 32, DIN / 32, NB), dim3(32, 32)>>>(
        conv_w, conv_b);

    // 3. x_proj split -> g_dt, g_BC (interleaved)
    xproj_kernel<<<dim3(LEN / 128, NB, 4), 128>>>(x_proj_w);

    // 4. delta = softplus(dt_proj) -> g_delta   (profiled slot)
    delta_kernel<<<dim3(LEN / 128, NB, 8), 128>>>(dt_proj_w, dt_proj_b);

    // 5. bidirectional scan v2.2 -> g_yf, g_yb
    scan_kernel<<<NB * (DIN / 8), 256, SC_SMEM>>>(A_log, Ab_log);

    // 6. fuse ysum = yf + yb + 2*D*xc -> g_yf
    fuse_kernel<<<1024, 256>>>(Dv);

    // 7. out_proj GEMM (tf32 HMMA, 2-stage, (d,l)-layout A) -> d_out
    gemm_tf32_kernel<1><<<dim3(DIM / 128, MTOT / 128), 256, GEMM_SMEM1>>>(
        nullptr, out_proj_w, out_proj_b, out);
}

// round 12
// speedup vs baseline: 1.1520x; 1.1155x over previous
#include <cuda_runtime.h>
#include <cuda_bf16.h>
#include <cstdint>

// Problem constants
#define BATCH   4
#define SEQ     6144
#define DIM     384
#define FCHUNK  3
#define NB      12      // BATCH*FCHUNK
#define LEN     2048    // SEQ/FCHUNK
#define DIN     192     // DIM/2
#define DSTATE  16
#define DTRANK  24
#define MTOT    (NB*LEN)    // 24576

// ---------------------------------------------------------------------------
// Scratch (static __device__ arrays; no allocation allowed)
// ---------------------------------------------------------------------------
__device__ float g_xp[MTOT * DIM];           // (12,2048,384) in_proj output
__device__ float g_xc[NB * DIN * LEN];       // (b,d,l) conv+silu output
__device__ float g_dt[NB * DTRANK * LEN];    // (b,r,l)
__device__ float g_Bm[NB * LEN * DSTATE];    // (b,l,n)
__device__ float g_Cm[NB * LEN * DSTATE];    // (b,l,n)
__device__ float g_delta[NB * DIN * LEN];    // (b,d,l)
__device__ float g_yf[NB * DIN * LEN];       // fwd scan out; later fused ysum
__device__ float g_yb[NB * DIN * LEN];       // bwd scan out (b,d,l)

// ---------------------------------------------------------------------------
// helpers
// ---------------------------------------------------------------------------
__device__ __forceinline__ uint32_t smem_u32(const void* p) {
    uint32_t a;
    asm("{ .reg .u64 t; cvta.to.shared.u64 t, %1; cvt.u32.u64 %0, t; }"
        : "=r"(a) : "l"(p));
    return a;
}
__device__ __forceinline__ uint32_t f2tf32(float x) {
    uint32_t r;
    asm("cvt.rna.tf32.f32 %0, %1;" : "=r"(r) : "f"(x));
    return r;
}
__device__ __forceinline__ void cp16(uint32_t dst, const void* src) {
    asm volatile("cp.async.ca.shared.global [%0], [%1], 16;"
                 :: "r"(dst), "l"(src) : "memory");
}
#define CP_COMMIT() asm volatile("cp.async.commit_group;" ::: "memory")
#define CP_WAIT1()  asm volatile("cp.async.wait_group 1;" ::: "memory")
#define CP_WAIT0()  asm volatile("cp.async.wait_group 0;" ::: "memory")

__device__ __forceinline__ void mma_tf32(float* c, const uint32_t* a,
                                         const uint32_t* b) {
    asm volatile(
        "mma.sync.aligned.m16n8k8.row.col.f32.tf32.tf32.f32 "
        "{%0,%1,%2,%3}, {%4,%5,%6,%7}, {%8,%9}, {%0,%1,%2,%3};"
        : "+f"(c[0]), "+f"(c[1]), "+f"(c[2]), "+f"(c[3])
        : "r"(a[0]), "r"(a[1]), "r"(a[2]), "r"(a[3]), "r"(b[0]), "r"(b[1]));
}

// ---------------------------------------------------------------------------
// tf32 HMMA GEMM: C[M,384] = A[M,384] @ W[384,384]^T + bias
// MODE 0: A plain row-major [m][k] (in_proj). MODE 1: A from (d,l) layout
// (k<192 -> g_yf fused ysum, else g_xc). 128x128 tile, BK=32,
// 2-stage cp.async pipeline (73.7KB smem -> 2 CTAs/SM).
// ---------------------------------------------------------------------------
#define AS_STRIDE0 36
#define AS_STRIDE1 136
#define BS_STRIDE  36
#define AS_F0 (128 * AS_STRIDE0)
#define AS_F1 (32 * AS_STRIDE1)
#define BS_F  (128 * BS_STRIDE)
#define GEMM_SMEM0 ((2 * (AS_F0 + BS_F)) * 4)   // 73728 B
#define GEMM_SMEM1 ((2 * (AS_F1 + BS_F)) * 4)   // 71680 B

template <int MODE>
__global__ __launch_bounds__(256, 2)
void gemm_tf32_kernel(const float* __restrict__ A,
                      const float* __restrict__ W,
                      const float* __restrict__ bias,
                      float* __restrict__ C)
{
    extern __shared__ float smf[];
    constexpr int AS_F = (MODE == 0) ? AS_F0 : AS_F1;
    float* AsBuf = smf;
    float* BsBuf = smf + 2 * AS_F;

    const int tid  = threadIdx.x;
    const int wid  = tid >> 5;
    const int lane = tid & 31;
    const int g = lane >> 2;
    const int t = lane & 3;
    const int wm = wid >> 1;
    const int wn = wid & 1;

    const int m0 = blockIdx.y * 128;
    const int n0 = blockIdx.x * 128;
    const int bb = m0 >> 11;
    const int lbase = m0 & 2047;

    const uint32_t sAu = smem_u32(AsBuf);
    const uint32_t sBu = smem_u32(BsBuf);

    float acc[2][8][4];
#pragma unroll
    for (int mt = 0; mt < 2; mt++)
#pragma unroll
        for (int nt = 0; nt < 8; nt++)
#pragma unroll
            for (int q = 0; q < 4; q++) acc[mt][nt][q] = 0.f;

    auto load_tile = [&](int kt, int buf) {
        const int k0 = kt * 32;
#pragma unroll
        for (int it = 0; it < 4; it++) {
            int idx = it * 256 + tid;
            int r = idx >> 3, c4 = idx & 7;
            uint32_t dst = sBu + (buf * BS_F + r * BS_STRIDE + c4 * 4) * 4;
            cp16(dst, &W[(n0 + r) * DIM + k0 + c4 * 4]);
        }
        if (MODE == 0) {
#pragma unroll
            for (int it = 0; it < 4; it++) {
                int idx = it * 256 + tid;
                int r = idx >> 3, c4 = idx & 7;
                uint32_t dst = sAu + (buf * AS_F + r * AS_STRIDE0 + c4 * 4) * 4;
                cp16(dst, &A[(m0 + r) * DIM + k0 + c4 * 4]);
            }
        } else {
            const float* srcb = (k0 < DIN)
                ? g_yf + ((size_t)(bb * DIN + k0) * LEN)
                : g_xc + ((size_t)(bb * DIN + (k0 - DIN)) * LEN);
#pragma unroll
            for (int it = 0; it < 4; it++) {
                int idx = it * 256 + tid;
                int kk = idx >> 5, m4 = idx & 31;
                uint32_t dst = sAu + (buf * AS_F + kk * AS_STRIDE1 + m4 * 4) * 4;
                cp16(dst, srcb + (size_t)kk * LEN + lbase + m4 * 4);
            }
        }
        CP_COMMIT();
    };

    load_tile(0, 0);

    for (int kt = 0; kt < 12; kt++) {
        if (kt + 1 < 12) {
            load_tile(kt + 1, (kt + 1) & 1);
            CP_WAIT1();
        } else {
            CP_WAIT0();
        }
        __syncthreads();

        const int buf = kt & 1;
        const float* As = AsBuf + buf * AS_F;
        const float* Bs = BsBuf + buf * BS_F;

#pragma unroll
        for (int s = 0; s < 4; s++) {
            uint32_t bf[8][2];
#pragma unroll
            for (int nt = 0; nt < 8; nt++) {
                int n = wn * 64 + nt * 8 + g;
                bf[nt][0] = f2tf32(Bs[n * BS_STRIDE + s * 8 + t]);
                bf[nt][1] = f2tf32(Bs[n * BS_STRIDE + s * 8 + t + 4]);
            }
#pragma unroll
            for (int mt = 0; mt < 2; mt++) {
                int row = wm * 32 + mt * 16 + g;
                uint32_t af[4];
                if (MODE == 0) {
                    af[0] = f2tf32(As[row * AS_STRIDE0 + s * 8 + t]);
                    af[1] = f2tf32(As[(row + 8) * AS_STRIDE0 + s * 8 + t]);
                    af[2] = f2tf32(As[row * AS_STRIDE0 + s * 8 + t + 4]);
                    af[3] = f2tf32(As[(row + 8) * AS_STRIDE0 + s * 8 + t + 4]);
                } else {
                    af[0] = f2tf32(As[(s * 8 + t) * AS_STRIDE1 + row]);
                    af[1] = f2tf32(As[(s * 8 + t) * AS_STRIDE1 + row + 8]);
                    af[2] = f2tf32(As[(s * 8 + t + 4) * AS_STRIDE1 + row]);
                    af[3] = f2tf32(As[(s * 8 + t + 4) * AS_STRIDE1 + row + 8]);
                }
#pragma unroll
                for (int nt = 0; nt < 8; nt++)
                    mma_tf32(acc[mt][nt], af, bf[nt]);
            }
        }
        __syncthreads();
    }

#pragma unroll
    for (int mt = 0; mt < 2; mt++) {
        int row = m0 + wm * 32 + mt * 16 + g;
#pragma unroll
        for (int nt = 0; nt < 8; nt++) {
            int col = n0 + wn * 64 + nt * 8 + t * 2;
            float b0 = bias[col], b1 = bias[col + 1];
            float2 v0 = make_float2(acc[mt][nt][0] + b0, acc[mt][nt][1] + b1);
            float2 v1 = make_float2(acc[mt][nt][2] + b0, acc[mt][nt][3] + b1);
            *(float2*)&C[(size_t)row * DIM + col] = v0;
            *(float2*)&C[(size_t)(row + 8) * DIM + col] = v1;
        }
    }
}

// ---------------------------------------------------------------------------
// Grouped conv (k=3, SAME, groups=192, 2 in-ch per group) + SiLU
// ---------------------------------------------------------------------------
__global__ __launch_bounds__(1024)
void conv_silu_kernel(const float* __restrict__ conv_w,
                      const float* __restrict__ conv_b)
{
    __shared__ float s[34][65];
    const int b  = blockIdx.z;
    const int d0 = blockIdx.y * 32;
    const int l0 = blockIdx.x * 32;
    const int tid = threadIdx.y * 32 + threadIdx.x;

    for (int e = tid; e < 34 * 64; e += 1024) {
        int li = e >> 6;
        int ci = e & 63;
        int l = l0 - 1 + li;
        float v = 0.f;
        if (l >= 0 && l < LEN)
            v = g_xp[(b * LEN + l) * DIM + 2 * d0 + ci];
        s[li][ci] = v;
    }
    __syncthreads();

    const int tx = threadIdx.x, ty = threadIdx.y;
    const int d = d0 + ty;
    float acc = conv_b[d];
    const float* w = conv_w + d * 6;
#pragma unroll
    for (int i = 0; i < 2; i++)
#pragma unroll
        for (int j = 0; j < 3; j++)
            acc = fmaf(s[tx + j][2 * ty + i], w[i * 3 + j], acc);
    float y = acc / (1.f + __expf(-acc));
    g_xc[(b * DIN + d) * LEN + l0 + tx] = y;
}

// ---------------------------------------------------------------------------
// x_proj: x_dbl[b,r,l] = sum_d W[r,d]*xc[b,d,l]; r-chunked over blockIdx.z
// ---------------------------------------------------------------------------
__global__ __launch_bounds__(128)
void xproj_kernel(const float* __restrict__ x_proj_w)
{
    __shared__ float sW[14 * DIN];
    const int b = blockIdx.y;
    const int l = blockIdx.x * 128 + threadIdx.x;
    const int r0 = blockIdx.z * 14;

    for (int i = threadIdx.x; i < 14 * DIN; i += 128)
        sW[i] = x_proj_w[r0 * DIN + i];
    __syncthreads();

    float acc[14];
#pragma unroll
    for (int j = 0; j < 14; j++) acc[j] = 0.f;

    for (int d = 0; d < DIN; d++) {
        float v = g_xc[(b * DIN + d) * LEN + l];
#pragma unroll
        for (int j = 0; j < 14; j++)
            acc[j] = fmaf(sW[j * DIN + d], v, acc[j]);
    }
#pragma unroll
    for (int j = 0; j < 14; j++) {
        int r = r0 + j;
        if (r < DTRANK)
            g_dt[(b * DTRANK + r) * LEN + l] = acc[j];
        else if (r < DTRANK + DSTATE)
            g_Bm[(b * LEN + l) * DSTATE + (r - DTRANK)] = acc[j];
        else
            g_Cm[(b * LEN + l) * DSTATE + (r - DTRANK - DSTATE)] = acc[j];
    }
}

// ---------------------------------------------------------------------------
// delta[b,d,l] = softplus(dt_proj_w[d,:].dt[b,:,l] + dt_proj_b[d]); d-chunk 24
// ---------------------------------------------------------------------------
__global__ __launch_bounds__(128)
void delta_kernel(const float* __restrict__ dt_proj_w,
                  const float* __restrict__ dt_proj_b)
{
    __shared__ float sW[24 * DTRANK];
    const int b = blockIdx.y;
    const int l = blockIdx.x * 128 + threadIdx.x;
    const int d0 = blockIdx.z * 24;

    for (int i = threadIdx.x; i < 24 * DTRANK; i += 128)
        sW[i] = dt_proj_w[d0 * DTRANK + i];
    __syncthreads();

    float dt[DTRANK];
#pragma unroll
    for (int r = 0; r < DTRANK; r++)
        dt[r] = g_dt[(b * DTRANK + r) * LEN + l];

#pragma unroll 4
    for (int j = 0; j < 24; j++) {
        int d = d0 + j;
        float a = dt_proj_b[d];
#pragma unroll
        for (int r = 0; r < DTRANK; r++)
            a = fmaf(sW[j * DTRANK + r], dt[r], a);
        float sp = (a > 20.f) ? a : log1pf(__expf(a));
        g_delta[(b * DIN + d) * LEN + l] = sp;
    }
}

// ---------------------------------------------------------------------------
// Bidirectional selective scan v2.3 — R9 skeleton + smem-transpose reduction
// (replaces the 12-shfl tree; h-recurrence and all operand loads unchanged).
// Block: 256 thr / 8 warps, owns (b, 8 consecutive d's).
//   warps 0-3: forward (d-locals {2w, 2w+1}), warps 4-7: backward (same).
// p-buffer: [dir][d][n*17 + t16] floats, conflict-free stores/loads;
// reduce every 16 timesteps: 256 threads sum 16 lanes each -> coalesced STG.
// smem: 2*6272 (double-buffered operands) + 2*8*272 (p-buffer) = 16896 fl.
// ---------------------------------------------------------------------------
#define SCHUNK   64
#define SC_BUF   6272
#define SC_DU    4096
#define PB_D     272                  // d-stride in p-buffer (16*17)
#define PB_DIR   (8 * PB_D)           // 2176
#define SC_SMEM  ((2 * SC_BUF + 2 * PB_DIR) * 4)   // 67584 B

__global__ __launch_bounds__(256)
void scan_kernel(const float* __restrict__ A_log,
                 const float* __restrict__ Ab_log)
{
    extern __shared__ float ss[];
    float* pbuf = ss + 2 * SC_BUF;
    const int b  = blockIdx.x / (DIN / 8);
    const int d0 = (blockIdx.x % (DIN / 8)) * 8;
    const int tid = threadIdx.x;
    const int wid = tid >> 5, lane = tid & 31;
    const bool bwd = wid >= 4;
    const int w = bwd ? wid - 4 : wid;
    const int half = lane >> 4, n = lane & 15;
    const int dloc = 2 * w + half;
    const int dg = d0 + dloc;

    const float Aval = -__expf(bwd ? Ab_log[dg * DSTATE + n]
                                   : A_log[dg * DSTATE + n]);
    // per-thread p-store base (dir, d, n fixed)
    float* pst = pbuf + (bwd ? PB_DIR : 0) + dloc * PB_D + n * 17;

    // reduce-phase mapping (independent of warp role)
    const int rdir = tid >> 7;            // 0 = fwd, 1 = bwd
    const int rrem = tid & 127;
    const int rd   = rrem >> 4;           // 0..7
    const int rt   = rrem & 15;           // 0..15
    const float* rq = pbuf + rdir * PB_DIR + rd * PB_D + rt;
    float* ybase = (rdir ? g_yb : g_yf) + (size_t)(b * DIN + d0 + rd) * LEN;

    const uint32_t sbase = smem_u32(ss);

    auto load_chunk = [&](int c, int buf) {
        const uint32_t dstb = sbase + (uint32_t)buf * SC_BUF * 4;
        const int lf = c * SCHUNK;
        const int lb = LEN - (c + 1) * SCHUNK;
#pragma unroll
        for (int it = 0; it < 4; it++) {
            int task = it * 256 + tid;
            int arr = task >> 8, r = task & 255;
            int lo = r >> 2, n4 = (r & 3) * 4;
            int ls = (arr < 2) ? lf + lo : lb + lo;
            const float* src = ((arr & 1) ? g_Cm : g_Bm)
                + ((size_t)(b * LEN + ls) * DSTATE + n4);
            cp16(dstb + (uint32_t)(arr * 1024 + lo * 16 + n4) * 4, src);
        }
#pragma unroll
        for (int it = 0; it < 2; it++) {
            int q = it * 256 + tid;
            int arr = q >> 7, s = q & 127;
            int dl = s >> 4, l4 = (s & 15) * 4;
            int ls = (arr < 2) ? lf + l4 : lb + l4;
            const float* src = ((arr & 1) ? g_xc : g_delta)
                + ((size_t)(b * DIN + d0 + dl) * LEN + ls);
            cp16(dstb + (uint32_t)(SC_DU + arr * 544 + dl * 68 + l4) * 4, src);
        }
    };

    float h = 0.f;
    load_chunk(0, 0);
    CP_COMMIT();

    for (int c = 0; c < LEN / SCHUNK; c++) {
        const int buf = c & 1;
        if (c + 1 < LEN / SCHUNK) load_chunk(c + 1, buf ^ 1);
        CP_COMMIT();
        CP_WAIT1();
        __syncthreads();

        const float* sm   = ss + buf * SC_BUF;
        const float* sB   = sm + (bwd ? 2048 : 0);
        const float* sC   = sB + 1024;
        const float* sdel = sm + SC_DU + (bwd ? 1088 : 0) + dloc * 68;
        const float* su   = sdel + 544;

#pragma unroll
        for (int w2 = 0; w2 < 4; w2++) {
            // ---- 4 groups (16 timesteps) ----
            if (!bwd) {
#pragma unroll
                for (int j = 0; j < 4; j++) {
                    const int t0 = (w2 * 4 + j) * 4;
#pragma unroll
                    for (int k = 0; k < 4; k++) {
                        int t = t0 + k;
                        float del = sdel[t], u = su[t];
                        float Bv = sB[t * 16 + n], Cv = sC[t * 16 + n];
                        float dA = __expf(del * Aval);
                        h = fmaf(dA, h, del * u * Bv);
                        pst[j * 4 + k] = h * Cv;
                    }
                }
            } else {
#pragma unroll
                for (int j = 0; j < 4; j++) {
                    const int t0 = (15 - (w2 * 4 + j)) * 4;
#pragma unroll
                    for (int k = 0; k < 4; k++) {
                        int t = t0 + 3 - k;
                        float del = sdel[t], u = su[t];
                        float Bv = sB[t * 16 + n], Cv = sC[t * 16 + n];
                        float dA = __expf(del * Aval);
                        h = fmaf(dA, h, del * u * Bv);
                        pst[(3 - j) * 4 + (3 - k)] = h * Cv;
                    }
                }
            }
            __syncthreads();
            // ---- reduce 16 timesteps: sum over n, write y ----
            {
                float s0 = 0.f, s1 = 0.f;
#pragma unroll
                for (int nn = 0; nn < 16; nn += 2) {
                    s0 += rq[nn * 17];
                    s1 += rq[(nn + 1) * 17];
                }
                int l = (rdir == 0)
                    ? (c * SCHUNK + w2 * 16 + rt)
                    : (LEN - (c + 1) * SCHUNK + (3 - w2) * 16 + rt);
                ybase[l] = s0 + s1;
            }
            __syncthreads();
        }
    }
}

// ---------------------------------------------------------------------------
// fuse: g_yf = yf + yb + 2*D[d]*xc   (elementwise, (b,d,l) layout)
// ---------------------------------------------------------------------------
__global__ __launch_bounds__(256)
void fuse_kernel(const float* __restrict__ Dv)
{
    const int total4 = NB * DIN * LEN / 4;
    for (int i4 = blockIdx.x * blockDim.x + threadIdx.x; i4 < total4;
         i4 += gridDim.x * blockDim.x) {
        int d = (i4 >> 9) % DIN;
        float dd = 2.f * Dv[d];
        float4 yf4 = ((const float4*)g_yf)[i4];
        float4 yb4 = ((const float4*)g_yb)[i4];
        float4 xc4 = ((const float4*)g_xc)[i4];
        float4 o;
        o.x = yf4.x + yb4.x + dd * xc4.x;
        o.y = yf4.y + yb4.y + dd * xc4.y;
        o.z = yf4.z + yb4.z + dd * xc4.z;
        o.w = yf4.w + yb4.w + dd * xc4.w;
        ((float4*)g_yf)[i4] = o;
    }
}

// ---------------------------------------------------------------------------
// Launch
// ---------------------------------------------------------------------------
extern "C" void kernel_launch(void* const* d_in, const int* in_sizes, int n_in,
                              void* d_out, int out_size)
{
    (void)in_sizes; (void)n_in; (void)out_size;
    const float* x          = (const float*)d_in[0];
    const float* in_proj_w  = (const float*)d_in[1];
    const float* in_proj_b  = (const float*)d_in[2];
    const float* conv_w     = (const float*)d_in[3];
    const float* conv_b     = (const float*)d_in[4];
    const float* A_log      = (const float*)d_in[5];
    const float* Ab_log     = (const float*)d_in[6];
    const float* Dv         = (const float*)d_in[7];
    const float* x_proj_w   = (const float*)d_in[8];
    const float* dt_proj_w  = (const float*)d_in[9];
    const float* dt_proj_b  = (const float*)d_in[10];
    const float* out_proj_w = (const float*)d_in[11];
    const float* out_proj_b = (const float*)d_in[12];
    float* out = (float*)d_out;

    float* xp_ptr;
    cudaGetSymbolAddress((void**)&xp_ptr, g_xp);

    cudaFuncSetAttribute(gemm_tf32_kernel<0>,
                         cudaFuncAttributeMaxDynamicSharedMemorySize, GEMM_SMEM0);
    cudaFuncSetAttribute(gemm_tf32_kernel<1>,
                         cudaFuncAttributeMaxDynamicSharedMemorySize, GEMM_SMEM1);
    cudaFuncSetAttribute(scan_kernel,
                         cudaFuncAttributeMaxDynamicSharedMemorySize, SC_SMEM);

    // 1. in_proj GEMM (tf32 HMMA, 2-stage, 2 CTA/SM) -> g_xp
    gemm_tf32_kernel<0><<<dim3(DIM / 128, MTOT / 128), 256, GEMM_SMEM0>>>(
        x, in_proj_w, in_proj_b, xp_ptr);

    // 2. conv + silu -> g_xc
    conv_silu_kernel<<<dim3(LEN / 32, DIN / 32, NB), dim3(32, 32)>>>(
        conv_w, conv_b);

    // 3. x_proj split -> g_dt, g_Bm, g_Cm
    xproj_kernel<<<dim3(LEN / 128, NB, 4), 128>>>(x_proj_w);

    // 4. delta = softplus(dt_proj) -> g_delta   (profiled slot)
    delta_kernel<<<dim3(LEN / 128, NB, 8), 128>>>(dt_proj_w, dt_proj_b);

    // 5. bidirectional scan v2.3 -> g_yf, g_yb
    scan_kernel<<<NB * (DIN / 8), 256, SC_SMEM>>>(A_log, Ab_log);

    // 6. fuse ysum = yf + yb + 2*D*xc -> g_yf
    fuse_kernel<<<1024, 256>>>(Dv);

    // 7. out_proj GEMM (tf32 HMMA, 2-stage, (d,l)-layout A) -> d_out
    gemm_tf32_kernel<1><<<dim3(DIM / 128, MTOT / 128), 256, GEMM_SMEM1>>>(
        nullptr, out_proj_w, out_proj_b, out);
}

// round 13
// speedup vs baseline: 1.1918x; 1.0346x over previous
#include <cuda_runtime.h>
#include <cuda_fp16.h>
#include <cstdint>

// Problem constants
#define BATCH   4
#define SEQ     6144
#define DIM     384
#define FCHUNK  3
#define NB      12      // BATCH*FCHUNK
#define LEN     2048    // SEQ/FCHUNK
#define DIN     192     // DIM/2
#define DSTATE  16
#define DTRANK  24
#define MTOT    (NB*LEN)    // 24576

// ---------------------------------------------------------------------------
// Scratch (static __device__ arrays; no allocation allowed)
// ---------------------------------------------------------------------------
__device__ float  g_xp[MTOT * DIM];           // in_proj output (fp32)
__device__ float  g_xc[NB * DIN * LEN];       // (b,d,l) conv+silu output
__device__ float  g_dt[NB * DTRANK * LEN];    // (b,r,l)
__device__ float  g_Bm[NB * LEN * DSTATE];    // (b,l,n)
__device__ float  g_Cm[NB * LEN * DSTATE];    // (b,l,n)
__device__ float  g_delta[NB * DIN * LEN];    // (b,d,l)
__device__ float  g_yf[NB * DIN * LEN];       // fwd scan out (b,d,l)
__device__ float  g_yb[NB * DIN * LEN];       // bwd scan out (b,d,l)
__device__ __half g_xh[MTOT * DIM];           // fp16 x
__device__ __half g_Ah[MTOT * DIM];           // fp16 [ysum | xc], row-major [m][384]
__device__ __half g_wih[DIM * DIM];           // fp16 in_proj_w
__device__ __half g_woh[DIM * DIM];           // fp16 out_proj_w

// ---------------------------------------------------------------------------
// helpers
// ---------------------------------------------------------------------------
__device__ __forceinline__ uint32_t smem_u32(const void* p) {
    uint32_t a;
    asm("{ .reg .u64 t; cvta.to.shared.u64 t, %1; cvt.u32.u64 %0, t; }"
        : "=r"(a) : "l"(p));
    return a;
}
__device__ __forceinline__ void cp16(uint32_t dst, const void* src) {
    asm volatile("cp.async.ca.shared.global [%0], [%1], 16;"
                 :: "r"(dst), "l"(src) : "memory");
}
#define CP_COMMIT() asm volatile("cp.async.commit_group;" ::: "memory")
#define CP_WAIT1()  asm volatile("cp.async.wait_group 1;" ::: "memory")
#define CP_WAIT0()  asm volatile("cp.async.wait_group 0;" ::: "memory")

__device__ __forceinline__ void mma_f16(float* c, const uint32_t* a,
                                        const uint32_t* b) {
    asm volatile(
        "mma.sync.aligned.m16n8k16.row.col.f32.f16.f16.f32 "
        "{%0,%1,%2,%3}, {%4,%5,%6,%7}, {%8,%9}, {%0,%1,%2,%3};"
        : "+f"(c[0]), "+f"(c[1]), "+f"(c[2]), "+f"(c[3])
        : "r"(a[0]), "r"(a[1]), "r"(a[2]), "r"(a[3]), "r"(b[0]), "r"(b[1]));
}

// ---------------------------------------------------------------------------
// cvt_half: fp32 -> fp16, float4-granular grid-stride
// ---------------------------------------------------------------------------
__global__ __launch_bounds__(256)
void cvt_half(const float* __restrict__ src, __half* __restrict__ dst, int n4)
{
    for (int i = blockIdx.x * blockDim.x + threadIdx.x; i < n4;
         i += gridDim.x * blockDim.x) {
        float4 v = ((const float4*)src)[i];
        __half2 h0 = __floats2half2_rn(v.x, v.y);
        __half2 h1 = __floats2half2_rn(v.z, v.w);
        ((__half2*)dst)[2 * i]     = h0;
        ((__half2*)dst)[2 * i + 1] = h1;
    }
}

// ---------------------------------------------------------------------------
// fp16 HMMA GEMM (unified): C[M,384] = A[M,384] @ W[384,384]^T + bias
// A, W row-major fp16 (pre-converted). 128x128 tile, BK=32 (2 ksteps of 16),
// 8 warps (4 M x 2 N), warp tile 32x64, 2-stage cp.async, 40KB smem.
// smem layout: As[row][40] halves (stride 20 banks -> conflict-free frags).
// ---------------------------------------------------------------------------
#define HS      40
#define TILE_H  (128 * HS)            // 5120 halves per array per stage
#define GEMM_SMEM_H (4 * TILE_H * 2)  // 40960 B

__global__ __launch_bounds__(256, 2)
void gemm_h_kernel(const __half* __restrict__ A,
                   const __half* __restrict__ W,
                   const float* __restrict__ bias,
                   float* __restrict__ C)
{
    extern __shared__ __half smh[];
    __half* AsBuf = smh;                   // 2 stages
    __half* BsBuf = smh + 2 * TILE_H;      // 2 stages

    const int tid  = threadIdx.x;
    const int wid  = tid >> 5;
    const int lane = tid & 31;
    const int g = lane >> 2;
    const int t = lane & 3;
    const int wm = wid >> 1;
    const int wn = wid & 1;

    const int m0 = blockIdx.y * 128;
    const int n0 = blockIdx.x * 128;

    const uint32_t sAu = smem_u32(AsBuf);
    const uint32_t sBu = smem_u32(BsBuf);

    float acc[2][8][4];
#pragma unroll
    for (int mt = 0; mt < 2; mt++)
#pragma unroll
        for (int nt = 0; nt < 8; nt++)
#pragma unroll
            for (int q = 0; q < 4; q++) acc[mt][nt][q] = 0.f;

    auto load_tile = [&](int kt, int buf) {
        const int k0 = kt * 32;
        // each tile: 128 rows x 32 halves = 512 granules of 16B; 2/thread
#pragma unroll
        for (int it = 0; it < 2; it++) {
            int idx = it * 256 + tid;
            int r = idx >> 2, c = idx & 3;
            cp16(sBu + (uint32_t)(buf * TILE_H + r * HS + c * 8) * 2,
                 &W[(size_t)(n0 + r) * DIM + k0 + c * 8]);
        }
#pragma unroll
        for (int it = 0; it < 2; it++) {
            int idx = it * 256 + tid;
            int r = idx >> 2, c = idx & 3;
            cp16(sAu + (uint32_t)(buf * TILE_H + r * HS + c * 8) * 2,
                 &A[(size_t)(m0 + r) * DIM + k0 + c * 8]);
        }
        CP_COMMIT();
    };

    load_tile(0, 0);

    for (int kt = 0; kt < 12; kt++) {
        if (kt + 1 < 12) {
            load_tile(kt + 1, (kt + 1) & 1);
            CP_WAIT1();
        } else {
            CP_WAIT0();
        }
        __syncthreads();

        const int buf = kt & 1;
        const __half* As = AsBuf + buf * TILE_H;
        const __half* Bs = BsBuf + buf * TILE_H;

#pragma unroll
        for (int s = 0; s < 2; s++) {
            const int kb = s * 16;
            uint32_t bf[8][2];
#pragma unroll
            for (int nt = 0; nt < 8; nt++) {
                int n = wn * 64 + nt * 8 + g;
                bf[nt][0] = *(const uint32_t*)&Bs[n * HS + kb + 2 * t];
                bf[nt][1] = *(const uint32_t*)&Bs[n * HS + kb + 2 * t + 8];
            }
#pragma unroll
            for (int mt = 0; mt < 2; mt++) {
                int row = wm * 32 + mt * 16 + g;
                uint32_t af[4];
                af[0] = *(const uint32_t*)&As[row * HS + kb + 2 * t];
                af[1] = *(const uint32_t*)&As[(row + 8) * HS + kb + 2 * t];
                af[2] = *(const uint32_t*)&As[row * HS + kb + 2 * t + 8];
                af[3] = *(const uint32_t*)&As[(row + 8) * HS + kb + 2 * t + 8];
#pragma unroll
                for (int nt = 0; nt < 8; nt++)
                    mma_f16(acc[mt][nt], af, bf[nt]);
            }
        }
        __syncthreads();
    }

#pragma unroll
    for (int mt = 0; mt < 2; mt++) {
        int row = m0 + wm * 32 + mt * 16 + g;
#pragma unroll
        for (int nt = 0; nt < 8; nt++) {
            int col = n0 + wn * 64 + nt * 8 + t * 2;
            float b0 = bias[col], b1 = bias[col + 1];
            float2 v0 = make_float2(acc[mt][nt][0] + b0, acc[mt][nt][1] + b1);
            float2 v1 = make_float2(acc[mt][nt][2] + b0, acc[mt][nt][3] + b1);
            *(float2*)&C[(size_t)row * DIM + col] = v0;
            *(float2*)&C[(size_t)(row + 8) * DIM + col] = v1;
        }
    }
}

// ---------------------------------------------------------------------------
// Grouped conv (k=3, SAME, groups=192, 2 in-ch per group) + SiLU  (R12 exact)
// ---------------------------------------------------------------------------
__global__ __launch_bounds__(1024)
void conv_silu_kernel(const float* __restrict__ conv_w,
                      const float* __restrict__ conv_b)
{
    __shared__ float s[34][65];
    const int b  = blockIdx.z;
    const int d0 = blockIdx.y * 32;
    const int l0 = blockIdx.x * 32;
    const int tid = threadIdx.y * 32 + threadIdx.x;

    for (int e = tid; e < 34 * 64; e += 1024) {
        int li = e >> 6;
        int ci = e & 63;
        int l = l0 - 1 + li;
        float v = 0.f;
        if (l >= 0 && l < LEN)
            v = g_xp[(b * LEN + l) * DIM + 2 * d0 + ci];
        s[li][ci] = v;
    }
    __syncthreads();

    const int tx = threadIdx.x, ty = threadIdx.y;
    const int d = d0 + ty;
    float acc = conv_b[d];
    const float* w = conv_w + d * 6;
#pragma unroll
    for (int i = 0; i < 2; i++)
#pragma unroll
        for (int j = 0; j < 3; j++)
            acc = fmaf(s[tx + j][2 * ty + i], w[i * 3 + j], acc);
    float y = acc / (1.f + __expf(-acc));
    g_xc[(b * DIN + d) * LEN + l0 + tx] = y;
}

// ---------------------------------------------------------------------------
// x_proj (R12 exact)
// ---------------------------------------------------------------------------
__global__ __launch_bounds__(128)
void xproj_kernel(const float* __restrict__ x_proj_w)
{
    __shared__ float sW[14 * DIN];
    const int b = blockIdx.y;
    const int l = blockIdx.x * 128 + threadIdx.x;
    const int r0 = blockIdx.z * 14;

    for (int i = threadIdx.x; i < 14 * DIN; i += 128)
        sW[i] = x_proj_w[r0 * DIN + i];
    __syncthreads();

    float acc[14];
#pragma unroll
    for (int j = 0; j < 14; j++) acc[j] = 0.f;

    for (int d = 0; d < DIN; d++) {
        float v = g_xc[(b * DIN + d) * LEN + l];
#pragma unroll
        for (int j = 0; j < 14; j++)
            acc[j] = fmaf(sW[j * DIN + d], v, acc[j]);
    }
#pragma unroll
    for (int j = 0; j < 14; j++) {
        int r = r0 + j;
        if (r < DTRANK)
            g_dt[(b * DTRANK + r) * LEN + l] = acc[j];
        else if (r < DTRANK + DSTATE)
            g_Bm[(b * LEN + l) * DSTATE + (r - DTRANK)] = acc[j];
        else
            g_Cm[(b * LEN + l) * DSTATE + (r - DTRANK - DSTATE)] = acc[j];
    }
}

// ---------------------------------------------------------------------------
// delta (R12 exact)
// ---------------------------------------------------------------------------
__global__ __launch_bounds__(128)
void delta_kernel(const float* __restrict__ dt_proj_w,
                  const float* __restrict__ dt_proj_b)
{
    __shared__ float sW[24 * DTRANK];
    const int b = blockIdx.y;
    const int l = blockIdx.x * 128 + threadIdx.x;
    const int d0 = blockIdx.z * 24;

    for (int i = threadIdx.x; i < 24 * DTRANK; i += 128)
        sW[i] = dt_proj_w[d0 * DTRANK + i];
    __syncthreads();

    float dt[DTRANK];
#pragma unroll
    for (int r = 0; r < DTRANK; r++)
        dt[r] = g_dt[(b * DTRANK + r) * LEN + l];

#pragma unroll 4
    for (int j = 0; j < 24; j++) {
        int d = d0 + j;
        float a = dt_proj_b[d];
#pragma unroll
        for (int r = 0; r < DTRANK; r++)
            a = fmaf(sW[j * DTRANK + r], dt[r], a);
        float sp = (a > 20.f) ? a : log1pf(__expf(a));
        g_delta[(b * DIN + d) * LEN + l] = sp;
    }
}

// ---------------------------------------------------------------------------
// Bidirectional selective scan v2.3 (R12 exact — smem-transpose reduction)
// ---------------------------------------------------------------------------
#define SCHUNK   64
#define SC_BUF   6272
#define SC_DU    4096
#define PB_D     272
#define PB_DIR   (8 * PB_D)
#define SC_SMEM  ((2 * SC_BUF + 2 * PB_DIR) * 4)   // 67584 B

__global__ __launch_bounds__(256)
void scan_kernel(const float* __restrict__ A_log,
                 const float* __restrict__ Ab_log)
{
    extern __shared__ float ss[];
    float* pbuf = ss + 2 * SC_BUF;
    const int b  = blockIdx.x / (DIN / 8);
    const int d0 = (blockIdx.x % (DIN / 8)) * 8;
    const int tid = threadIdx.x;
    const int wid = tid >> 5, lane = tid & 31;
    const bool bwd = wid >= 4;
    const int w = bwd ? wid - 4 : wid;
    const int half = lane >> 4, n = lane & 15;
    const int dloc = 2 * w + half;
    const int dg = d0 + dloc;

    const float Aval = -__expf(bwd ? Ab_log[dg * DSTATE + n]
                                   : A_log[dg * DSTATE + n]);
    float* pst = pbuf + (bwd ? PB_DIR : 0) + dloc * PB_D + n * 17;

    const int rdir = tid >> 7;
    const int rrem = tid & 127;
    const int rd   = rrem >> 4;
    const int rt   = rrem & 15;
    const float* rq = pbuf + rdir * PB_DIR + rd * PB_D + rt;
    float* ybase = (rdir ? g_yb : g_yf) + (size_t)(b * DIN + d0 + rd) * LEN;

    const uint32_t sbase = smem_u32(ss);

    auto load_chunk = [&](int c, int buf) {
        const uint32_t dstb = sbase + (uint32_t)buf * SC_BUF * 4;
        const int lf = c * SCHUNK;
        const int lb = LEN - (c + 1) * SCHUNK;
#pragma unroll
        for (int it = 0; it < 4; it++) {
            int task = it * 256 + tid;
            int arr = task >> 8, r = task & 255;
            int lo = r >> 2, n4 = (r & 3) * 4;
            int ls = (arr < 2) ? lf + lo : lb + lo;
            const float* src = ((arr & 1) ? g_Cm : g_Bm)
                + ((size_t)(b * LEN + ls) * DSTATE + n4);
            cp16(dstb + (uint32_t)(arr * 1024 + lo * 16 + n4) * 4, src);
        }
#pragma unroll
        for (int it = 0; it < 2; it++) {
            int q = it * 256 + tid;
            int arr = q >> 7, s = q & 127;
            int dl = s >> 4, l4 = (s & 15) * 4;
            int ls = (arr < 2) ? lf + l4 : lb + l4;
            const float* src = ((arr & 1) ? g_xc : g_delta)
                + ((size_t)(b * DIN + d0 + dl) * LEN + ls);
            cp16(dstb + (uint32_t)(SC_DU + arr * 544 + dl * 68 + l4) * 4, src);
        }
    };

    float h = 0.f;
    load_chunk(0, 0);
    CP_COMMIT();

    for (int c = 0; c < LEN / SCHUNK; c++) {
        const int buf = c & 1;
        if (c + 1 < LEN / SCHUNK) load_chunk(c + 1, buf ^ 1);
        CP_COMMIT();
        CP_WAIT1();
        __syncthreads();

        const float* sm   = ss + buf * SC_BUF;
        const float* sB   = sm + (bwd ? 2048 : 0);
        const float* sC   = sB + 1024;
        const float* sdel = sm + SC_DU + (bwd ? 1088 : 0) + dloc * 68;
        const float* su   = sdel + 544;

#pragma unroll
        for (int w2 = 0; w2 < 4; w2++) {
            if (!bwd) {
#pragma unroll
                for (int j = 0; j < 4; j++) {
                    const int t0 = (w2 * 4 + j) * 4;
#pragma unroll
                    for (int k = 0; k < 4; k++) {
                        int t = t0 + k;
                        float del = sdel[t], u = su[t];
                        float Bv = sB[t * 16 + n], Cv = sC[t * 16 + n];
                        float dA = __expf(del * Aval);
                        h = fmaf(dA, h, del * u * Bv);
                        pst[j * 4 + k] = h * Cv;
                    }
                }
            } else {
#pragma unroll
                for (int j = 0; j < 4; j++) {
                    const int t0 = (15 - (w2 * 4 + j)) * 4;
#pragma unroll
                    for (int k = 0; k < 4; k++) {
                        int t = t0 + 3 - k;
                        float del = sdel[t], u = su[t];
                        float Bv = sB[t * 16 + n], Cv = sC[t * 16 + n];
                        float dA = __expf(del * Aval);
                        h = fmaf(dA, h, del * u * Bv);
                        pst[(3 - j) * 4 + (3 - k)] = h * Cv;
                    }
                }
            }
            __syncthreads();
            {
                float s0 = 0.f, s1 = 0.f;
#pragma unroll
                for (int nn = 0; nn < 16; nn += 2) {
                    s0 += rq[nn * 17];
                    s1 += rq[(nn + 1) * 17];
                }
                int l = (rdir == 0)
                    ? (c * SCHUNK + w2 * 16 + rt)
                    : (LEN - (c + 1) * SCHUNK + (3 - w2) * 16 + rt);
                ybase[l] = s0 + s1;
            }
            __syncthreads();
        }
    }
}

// ---------------------------------------------------------------------------
// fuse_T: transpose + add + fp16 pack.
// reads yf/yb/xc (b,d,l); writes g_Ah[(b*LEN+l)*384 + d] = ysum (fp16),
//                                g_Ah[... + 192 + d]     = xc   (fp16)
// block (32,32): d-tile x l-tile; coalesced both phases.
// ---------------------------------------------------------------------------
__global__ __launch_bounds__(1024)
void fuse_T_kernel(const float* __restrict__ Dv)
{
    __shared__ float sy[32][33];
    __shared__ float sz[32][33];
    const int b  = blockIdx.z;
    const int d0 = blockIdx.y * 32;
    const int l0 = blockIdx.x * 32;
    const int tx = threadIdx.x, ty = threadIdx.y;

    const int d = d0 + ty;
    const size_t off = (size_t)(b * DIN + d) * LEN + l0 + tx;
    float yf = g_yf[off];
    float yb = g_yb[off];
    float xc = g_xc[off];
    sy[ty][tx] = yf + yb + 2.f * Dv[d] * xc;
    sz[ty][tx] = xc;
    __syncthreads();

    __half* dst = g_Ah + (size_t)(b * LEN + l0 + ty) * DIM;
    dst[d0 + tx]       = __float2half_rn(sy[tx][ty]);
    dst[DIN + d0 + tx] = __float2half_rn(sz[tx][ty]);
}

// ---------------------------------------------------------------------------
// Launch
// ---------------------------------------------------------------------------
extern "C" void kernel_launch(void* const* d_in, const int* in_sizes, int n_in,
                              void* d_out, int out_size)
{
    (void)in_sizes; (void)n_in; (void)out_size;
    const float* x          = (const float*)d_in[0];
    const float* in_proj_w  = (const float*)d_in[1];
    const float* in_proj_b  = (const float*)d_in[2];
    const float* conv_w     = (const float*)d_in[3];
    const float* conv_b     = (const float*)d_in[4];
    const float* A_log      = (const float*)d_in[5];
    const float* Ab_log     = (const float*)d_in[6];
    const float* Dv         = (const float*)d_in[7];
    const float* x_proj_w   = (const float*)d_in[8];
    const float* dt_proj_w  = (const float*)d_in[9];
    const float* dt_proj_b  = (const float*)d_in[10];
    const float* out_proj_w = (const float*)d_in[11];
    const float* out_proj_b = (const float*)d_in[12];
    float* out = (float*)d_out;

    float* xp_ptr;
    __half *xh_ptr, *ah_ptr, *wih_ptr, *woh_ptr;
    cudaGetSymbolAddress((void**)&xp_ptr, g_xp);
    cudaGetSymbolAddress((void**)&xh_ptr, g_xh);
    cudaGetSymbolAddress((void**)&ah_ptr, g_Ah);
    cudaGetSymbolAddress((void**)&wih_ptr, g_wih);
    cudaGetSymbolAddress((void**)&woh_ptr, g_woh);

    cudaFuncSetAttribute(scan_kernel,
                         cudaFuncAttributeMaxDynamicSharedMemorySize, SC_SMEM);

    // 1-3. fp16 pre-conversion
    cvt_half<<<144, 256>>>(in_proj_w, wih_ptr, DIM * DIM / 4);
    cvt_half<<<144, 256>>>(out_proj_w, woh_ptr, DIM * DIM / 4);
    cvt_half<<<1024, 256>>>(x, xh_ptr, MTOT * DIM / 4);

    // 4. in_proj GEMM (fp16 HMMA)  [profiled slot]
    gemm_h_kernel<<<dim3(DIM / 128, MTOT / 128), 256, GEMM_SMEM_H>>>(
        xh_ptr, wih_ptr, in_proj_b, xp_ptr);

    // 5. conv + silu -> g_xc
    conv_silu_kernel<<<dim3(LEN / 32, DIN / 32, NB), dim3(32, 32)>>>(
        conv_w, conv_b);

    // 6. x_proj split -> g_dt, g_Bm, g_Cm
    xproj_kernel<<<dim3(LEN / 128, NB, 4), 128>>>(x_proj_w);

    // 7. delta = softplus(dt_proj) -> g_delta
    delta_kernel<<<dim3(LEN / 128, NB, 8), 128>>>(dt_proj_w, dt_proj_b);

    // 8. bidirectional scan v2.3 -> g_yf, g_yb
    scan_kernel<<<NB * (DIN / 8), 256, SC_SMEM>>>(A_log, Ab_log);

    // 9. fuse + transpose -> g_Ah (fp16 [m][384])
    fuse_T_kernel<<<dim3(LEN / 32, DIN / 32, NB), dim3(32, 32)>>>(Dv);

    // 10. out_proj GEMM (fp16 HMMA) -> d_out
    gemm_h_kernel<<<dim3(DIM / 128, MTOT / 128), 256, GEMM_SMEM_H>>>(
        ah_ptr, woh_ptr, out_proj_b, out);
}